// round 8
// baseline (speedup 1.0000x reference)
#include <cuda_runtime.h>

// out = y where 0 < y <= 1 else 0, y = x * w[col] + b[col]
// x: [8192, 4096] f32, w/b: [4096] f32. HBM-bound elementwise.
// R8: exact R2 structure (best: 37.95us kernel) but with DEFAULT write-back
//     stores instead of __stcs — let the 126MB L2 buffer the write stream
//     into long DRAM bursts (less read/write turnaround) and defer part of
//     the drain past kernel end.

#define D_VEC 1024            // 4096/4
#define ITEMS 4
#define THREADS 256
#define CHUNK (THREADS * ITEMS)   // 1024 == D_VEC

__global__ void __launch_bounds__(THREADS)
gegate_kernel(const float4* __restrict__ x,
              const float4* __restrict__ w,
              const float4* __restrict__ b,
              float4* __restrict__ out)
{
    const int t = threadIdx.x;
    const int base = blockIdx.x * CHUNK + t;

    // Front-batched streaming reads: 4 independent DRAM loads in flight.
    float4 xv[ITEMS];
    #pragma unroll
    for (int i = 0; i < ITEMS; i++)
        xv[i] = __ldcs(&x[base + i * THREADS]);

    #pragma unroll
    for (int i = 0; i < ITEMS; i++) {
        const int col = (base + i * THREADS) & (D_VEC - 1);
        float4 wv = __ldg(&w[col]);
        float4 bv = __ldg(&b[col]);
        float4 y;
        y.x = fmaf(xv[i].x, wv.x, bv.x);
        y.y = fmaf(xv[i].y, wv.y, bv.y);
        y.z = fmaf(xv[i].z, wv.z, bv.z);
        y.w = fmaf(xv[i].w, wv.w, bv.w);
        y.x = (y.x > 0.0f && y.x <= 1.0f) ? y.x : 0.0f;
        y.y = (y.y > 0.0f && y.y <= 1.0f) ? y.y : 0.0f;
        y.z = (y.z > 0.0f && y.z <= 1.0f) ? y.z : 0.0f;
        y.w = (y.w > 0.0f && y.w <= 1.0f) ? y.w : 0.0f;
        out[base + i * THREADS] = y;      // default .wb store
    }
}

extern "C" void kernel_launch(void* const* d_in, const int* in_sizes, int n_in,
                              void* d_out, int out_size)
{
    const float4* x = (const float4*)d_in[0];
    const float4* w = (const float4*)d_in[1];
    const float4* b = (const float4*)d_in[2];
    float4* out = (float4*)d_out;

    int n_vec = out_size / 4;             // 8388608
    int blocks = n_vec / CHUNK;           // 8192 exactly

    gegate_kernel<<<blocks, THREADS>>>(x, w, b, out);
}

// round 9
// speedup vs baseline: 1.0135x; 1.0135x over previous
#include <cuda_runtime.h>

// out = y where 0 < y <= 1 else 0, y = x * w[col] + b[col]
// x: [8192, 4096] f32, w/b: [4096] f32. HBM-bound elementwise.
// R9 FINAL = R2 (measured best: kernel 37.95us, bench 44.70us, ~88% of HBM
// spec wall-clock). Flat grid, 4 float4/thread, front-batched streaming x
// reads, JIT read-only w/b loads, streaming stores. Rounds 3-8 established
// that occupancy (41-82%), MLP (1-8), vector width (v4/v8), smem staging,
// persistence, and store cache policy are all neutral or worse: the kernel
// sits on the mixed read+write DRAM ceiling.

#define D_VEC 1024            // 4096 / 4, power of two
#define ITEMS 4               // float4s per thread
#define THREADS 256
#define CHUNK (THREADS * ITEMS)   // 1024 float4 per block

__device__ __forceinline__ float4 gate4(float4 xv, float4 wv, float4 bv)
{
    float4 y;
    y.x = fmaf(xv.x, wv.x, bv.x);
    y.y = fmaf(xv.y, wv.y, bv.y);
    y.z = fmaf(xv.z, wv.z, bv.z);
    y.w = fmaf(xv.w, wv.w, bv.w);
    y.x = (y.x > 0.0f && y.x <= 1.0f) ? y.x : 0.0f;
    y.y = (y.y > 0.0f && y.y <= 1.0f) ? y.y : 0.0f;
    y.z = (y.z > 0.0f && y.z <= 1.0f) ? y.z : 0.0f;
    y.w = (y.w > 0.0f && y.w <= 1.0f) ? y.w : 0.0f;
    return y;
}

__global__ void __launch_bounds__(THREADS)
gegate_kernel(const float4* __restrict__ x,
              const float4* __restrict__ w,
              const float4* __restrict__ b,
              float4* __restrict__ out)
{
    // Each block covers CHUNK consecutive float4s; thread t handles
    // base + i*THREADS (fully coalesced, 4 independent DRAM loads in flight).
    int base = blockIdx.x * CHUNK + threadIdx.x;

    float4 xv[ITEMS];
    #pragma unroll
    for (int i = 0; i < ITEMS; i++)
        xv[i] = __ldcs(&x[base + i * THREADS]);   // streaming: no L2 reuse

    #pragma unroll
    for (int i = 0; i < ITEMS; i++) {
        int idx = base + i * THREADS;
        int col = idx & (D_VEC - 1);
        float4 wv = __ldg(&w[col]);
        float4 bv = __ldg(&b[col]);
        __stcs(&out[idx], gate4(xv[i], wv, bv));
    }
}

extern "C" void kernel_launch(void* const* d_in, const int* in_sizes, int n_in,
                              void* d_out, int out_size)
{
    const float4* x = (const float4*)d_in[0];
    const float4* w = (const float4*)d_in[1];
    const float4* b = (const float4*)d_in[2];
    float4* out = (float4*)d_out;

    int n_vec = out_size / 4;                     // 8388608
    int blocks = n_vec / CHUNK;                   // 8192 exactly

    gegate_kernel<<<blocks, THREADS>>>(x, w, b, out);
}